// round 7
// baseline (speedup 1.0000x reference)
#include <cuda_runtime.h>
#include <cstdint>

// Problem constants
#define NN 50000
#define DD 128
#define EE 625000

typedef unsigned long long u64;

// Scratch (allocation-free rule: __device__ globals)
__device__ float g_agg[(size_t)NN * DD];
__device__ float g_h[(size_t)NN * DD];
__device__ int g_deg[NN];
__device__ int g_row[NN + 1];
__device__ int g_cdst[EE];

// ---------------------------------------------------------------------------
// Zero kernels
// ---------------------------------------------------------------------------
__global__ void zero_kernel(float4* __restrict__ p, int n4) {
    int i = blockIdx.x * blockDim.x + threadIdx.x;
    if (i < n4) p[i] = make_float4(0.f, 0.f, 0.f, 0.f);
}
__global__ void zero_deg_kernel(int* __restrict__ deg) {
    int i = blockIdx.x * blockDim.x + threadIdx.x;
    if (i < NN) deg[i] = 0;
}

// ---------------------------------------------------------------------------
// src-CSR build: histogram by SRC -> scan -> fill dst list sorted by src.
// ---------------------------------------------------------------------------
__global__ void hist_kernel(const int* __restrict__ ei, int* __restrict__ deg) {
    int e = blockIdx.x * blockDim.x + threadIdx.x;
    if (e < EE) atomicAdd(&deg[ei[e]], 1);   // key = src
}

__global__ __launch_bounds__(1024, 1)
void scan_kernel(int* __restrict__ deg, int* __restrict__ row) {
    __shared__ int partial[1024];
    int tid = threadIdx.x;
    const int chunk = (NN + 1023) / 1024;  // 49
    int start = tid * chunk;
    int mysum = 0;
    for (int i = 0; i < chunk; i++) {
        int idx = start + i;
        if (idx < NN) mysum += deg[idx];
    }
    partial[tid] = mysum;
    __syncthreads();
    for (int off = 1; off < 1024; off <<= 1) {
        int v = (tid >= off) ? partial[tid - off] : 0;
        __syncthreads();
        partial[tid] += v;
        __syncthreads();
    }
    int run = partial[tid] - mysum;
    for (int i = 0; i < chunk; i++) {
        int idx = start + i;
        if (idx < NN) {
            row[idx] = run;
            run += deg[idx];
            deg[idx] = 0;   // reuse deg as fill cursor
        }
    }
    if (tid == 0) row[NN] = EE;
}

__global__ void fill_kernel(const int* __restrict__ ei,
                            const int* __restrict__ row,
                            int* __restrict__ cur,
                            int* __restrict__ cdst) {
    int e = blockIdx.x * blockDim.x + threadIdx.x;
    if (e < EE) {
        int s = ei[e];
        int pos = row[s] + atomicAdd(&cur[s], 1);
        cdst[pos] = ei[EE + e];
    }
}

// ---------------------------------------------------------------------------
// src-side scatter: one warp per SRC node.
//   Load feat[s] ONCE into registers, then RED it to every neighbor dst.
//   Reads: 25.6 MB streaming (vs 320 MB random). Writes: fire-and-forget REDs.
// ---------------------------------------------------------------------------
__device__ __forceinline__ void red4(float* dp, float4 a) {
    asm volatile("red.global.add.v4.f32 [%0], {%1, %2, %3, %4};"
                 :: "l"(dp), "f"(a.x), "f"(a.y), "f"(a.z), "f"(a.w)
                 : "memory");
}

__global__ __launch_bounds__(256, 1)
void srcscatter_kernel(const float* __restrict__ feat,
                       const int* __restrict__ row,
                       const int* __restrict__ cdst,
                       float* __restrict__ agg) {
    int s = (blockIdx.x * blockDim.x + threadIdx.x) >> 5;
    int lane = threadIdx.x & 31;
    if (s >= NN) return;
    int beg = __ldg(&row[s]);
    int end = __ldg(&row[s + 1]);
    if (beg == end) return;

    float4 v = ((const float4*)(feat + (size_t)s * DD))[lane];

    for (int b = beg; b < end; b += 32) {
        int n = min(32, end - b);
        int myd = (lane < n) ? __ldg(&cdst[b + lane]) : 0;
#pragma unroll 4
        for (int t = 0; t < n; t++) {
            int d = __shfl_sync(0xffffffffu, myd, t);
            red4(agg + (size_t)d * DD + lane * 4, v);
        }
    }
}

// ---------------------------------------------------------------------------
// Persistent fused dual GEMM with packed f32x2 FMA (FFMA2).
// grid = 148 (one CTA per SM); each CTA loops over 128-row tiles.
// Weights staged to smem ONCE per CTA; A/X staged per tile in 64-k chunks.
// ---------------------------------------------------------------------------
#define KT 64
#define AST 68
#define NTILES ((NN + 127) / 128)   // 391
#define GEMM_GRID 148
#define GEMM_SMEM ((2 * 128 * 128 + 2 * 128 * AST) * sizeof(float))

__device__ __forceinline__ u64 pack2(float a) {
    u64 r;
    asm("mov.b64 %0, {%1, %1};" : "=l"(r) : "f"(a));
    return r;
}
__device__ __forceinline__ u64 ffma2(u64 a, u64 b, u64 c) {
    u64 d;
    asm("fma.rn.f32x2 %0, %1, %2, %3;" : "=l"(d) : "l"(a), "l"(b), "l"(c));
    return d;
}

__global__ __launch_bounds__(256, 1)
void gemm_kernel(const float* __restrict__ A,
                 const float* __restrict__ X,
                 const float* __restrict__ Wrel,
                 const float* __restrict__ Wroot,
                 const float* __restrict__ bias,
                 float* __restrict__ out,
                 int relu) {
    extern __shared__ float sm[];
    float* Wr = sm;
    float* Wo = Wr + 128 * 128;
    float* As = Wo + 128 * 128;
    float* Xs = As + 128 * AST;

    int tid = threadIdx.x;
    int tx = tid & 15;
    int ty = tid >> 4;

    // Stage both weight matrices once per CTA
    for (int i = tid; i < 128 * 128 / 4; i += 256) {
        ((float4*)Wr)[i] = ((const float4*)Wrel)[i];
        ((float4*)Wo)[i] = ((const float4*)Wroot)[i];
    }

    float b0[4], b1[4];
#pragma unroll
    for (int j = 0; j < 4; j++) {
        int c = tx * 2 + j * 32;
        b0[j] = __ldg(&bias[c]);
        b1[j] = __ldg(&bias[c + 1]);
    }

    for (int bt = blockIdx.x; bt < NTILES; bt += GEMM_GRID) {
        int row0 = bt * 128;

        u64 acc[8][4];
#pragma unroll
        for (int i = 0; i < 8; i++)
#pragma unroll
            for (int j = 0; j < 4; j++) acc[i][j] = 0ull;

        for (int stage = 0; stage < 2; stage++) {
            int kb = stage * KT;
            __syncthreads();   // protect As/Xs reuse (prev stage/tile readers)
            for (int i = tid; i < 128 * 16; i += 256) {
                int r = i >> 4, c = i & 15;
                int grow = row0 + r;
                float4 av, xv;
                if (grow < NN) {
                    av = ((const float4*)(A + (size_t)grow * DD + kb))[c];
                    xv = ((const float4*)(X + (size_t)grow * DD + kb))[c];
                } else {
                    av = make_float4(0.f, 0.f, 0.f, 0.f);
                    xv = av;
                }
                ((float4*)(As + r * AST))[c] = av;
                ((float4*)(Xs + r * AST))[c] = xv;
            }
            __syncthreads();

#pragma unroll 2
            for (int kk = 0; kk < KT; kk++) {
                const float* wrk = Wr + (kb + kk) * 128;
                const float* wok = Wo + (kb + kk) * 128;
                u64 wr2[4], wo2[4];
#pragma unroll
                for (int j = 0; j < 4; j++) {
                    wr2[j] = *(const u64*)(wrk + tx * 2 + j * 32);
                    wo2[j] = *(const u64*)(wok + tx * 2 + j * 32);
                }
                u64 a2[8], x2[8];
#pragma unroll
                for (int i = 0; i < 8; i++) {
                    a2[i] = pack2(As[(ty * 8 + i) * AST + kk]);
                    x2[i] = pack2(Xs[(ty * 8 + i) * AST + kk]);
                }
#pragma unroll
                for (int i = 0; i < 8; i++)
#pragma unroll
                    for (int j = 0; j < 4; j++) {
                        acc[i][j] = ffma2(a2[i], wr2[j], acc[i][j]);
                        acc[i][j] = ffma2(x2[i], wo2[j], acc[i][j]);
                    }
            }
        }

#pragma unroll
        for (int i = 0; i < 8; i++) {
            int grow = row0 + ty * 8 + i;
            if (grow < NN) {
#pragma unroll
                for (int j = 0; j < 4; j++) {
                    int c = tx * 2 + j * 32;
                    float lo, hi;
                    asm("mov.b64 {%0, %1}, %2;" : "=f"(lo), "=f"(hi) : "l"(acc[i][j]));
                    lo += b0[j];
                    hi += b1[j];
                    if (relu) { lo = fmaxf(lo, 0.f); hi = fmaxf(hi, 0.f); }
                    *(float2*)(out + (size_t)grow * DD + c) = make_float2(lo, hi);
                }
            }
        }
    }
}

// ---------------------------------------------------------------------------
// Launch
// ---------------------------------------------------------------------------
extern "C" void kernel_launch(void* const* d_in, const int* in_sizes, int n_in,
                              void* d_out, int out_size) {
    const float* x       = (const float*)d_in[0];
    const int*   ei      = (const int*)d_in[1];   // int32 (JAX x64 disabled)
    const float* W1_rel  = (const float*)d_in[2];
    const float* b1_rel  = (const float*)d_in[3];
    const float* W1_root = (const float*)d_in[4];
    const float* W2_rel  = (const float*)d_in[5];
    const float* b2_rel  = (const float*)d_in[6];
    const float* W2_root = (const float*)d_in[7];
    float*       out     = (float*)d_out;

    float *agg, *h;
    int *deg, *row, *cdst;
    cudaGetSymbolAddress((void**)&agg, g_agg);
    cudaGetSymbolAddress((void**)&h, g_h);
    cudaGetSymbolAddress((void**)&deg, g_deg);
    cudaGetSymbolAddress((void**)&row, g_row);
    cudaGetSymbolAddress((void**)&cdst, g_cdst);

    cudaFuncSetAttribute(gemm_kernel,
                         cudaFuncAttributeMaxDynamicSharedMemorySize,
                         (int)GEMM_SMEM);

    const int n4 = NN * DD / 4;
    const int zgrid = (n4 + 255) / 256;
    const int egrid = (EE + 255) / 256;
    const int ngrid = (NN + 255) / 256;
    const int wgrid = (NN * 32 + 255) / 256;   // warp per src node

    // Build src-CSR (once; shared by both layers)
    zero_deg_kernel<<<ngrid, 256>>>(deg);
    hist_kernel<<<egrid, 256>>>(ei, deg);
    scan_kernel<<<1, 1024>>>(deg, row);          // also resets deg -> cursors
    fill_kernel<<<egrid, 256>>>(ei, row, deg, cdst);

    // Layer 1
    zero_kernel<<<zgrid, 256>>>((float4*)agg, n4);
    srcscatter_kernel<<<wgrid, 256>>>(x, row, cdst, agg);
    gemm_kernel<<<GEMM_GRID, 256, GEMM_SMEM>>>(agg, x, W1_rel, W1_root, b1_rel, h, 1);

    // Layer 2
    zero_kernel<<<zgrid, 256>>>((float4*)agg, n4);
    srcscatter_kernel<<<wgrid, 256>>>(h, row, cdst, agg);
    gemm_kernel<<<GEMM_GRID, 256, GEMM_SMEM>>>(agg, h, W2_rel, W2_root, b2_rel, out, 0);
}

// round 8
// speedup vs baseline: 1.3868x; 1.3868x over previous
#include <cuda_runtime.h>
#include <cuda_fp16.h>
#include <cstdint>

// Problem constants
#define NN 50000
#define DD 128
#define EE 625000

typedef unsigned long long u64;

// Scratch (allocation-free rule: __device__ globals)
__device__ float  g_h[(size_t)NN * DD];        // layer-1 output (fp32)
__device__ __half g_feat16[(size_t)NN * DD];   // fp16 features (x16, then h16)
__device__ __half g_agg16[(size_t)NN * DD];    // fp16 aggregation buffer

// ---------------------------------------------------------------------------
// Zero kernel (float4-wide; also used for the fp16 buffer via cast)
// ---------------------------------------------------------------------------
__global__ void zero_kernel(float4* __restrict__ p, int n4) {
    int i = blockIdx.x * blockDim.x + threadIdx.x;
    if (i < n4) p[i] = make_float4(0.f, 0.f, 0.f, 0.f);
}

// ---------------------------------------------------------------------------
// fp32 -> fp16 convert (x -> x16), 4 elems/thread
// ---------------------------------------------------------------------------
__global__ void tohalf_kernel(const float4* __restrict__ src,
                              uint2* __restrict__ dst, int n4) {
    int i = blockIdx.x * blockDim.x + threadIdx.x;
    if (i < n4) {
        float4 v = src[i];
        __half2 a = __floats2half2_rn(v.x, v.y);
        __half2 b = __floats2half2_rn(v.z, v.w);
        dst[i] = make_uint2(*(unsigned*)&a, *(unsigned*)&b);
    }
}

// ---------------------------------------------------------------------------
// fp16 scatter-aggregate: one warp per 8 edges.
//   agg16[dst] += feat16[src]; row = 256B; lane handles 4 halves (8B).
//   red.global.add.noftz.v2.f16x2 — halves the random L2 traffic vs fp32.
// ---------------------------------------------------------------------------
#define EPW 8
__global__ void scatter16_kernel(const __half* __restrict__ feat,
                                 const int* __restrict__ ei,
                                 __half* __restrict__ agg) {
    int gw = (blockIdx.x * blockDim.x + threadIdx.x) >> 5;
    int lane = threadIdx.x & 31;
    int e0 = gw * EPW;
    if (e0 >= EE) return;
    int cnt = min(EPW, EE - e0);

    uint2 v[EPW];
    int d[EPW];
#pragma unroll
    for (int t = 0; t < EPW; t++) {
        if (t < cnt) {
            int e = e0 + t;
            int s = __ldg(&ei[e]);
            d[t] = __ldg(&ei[EE + e]);
            v[t] = ((const uint2*)(feat + (size_t)s * DD))[lane];
        }
    }
#pragma unroll
    for (int t = 0; t < EPW; t++) {
        if (t < cnt) {
            const __half* dp = agg + (size_t)d[t] * DD + lane * 4;
            asm volatile("red.global.add.noftz.v2.f16x2 [%0], {%1, %2};"
                         :: "l"(dp), "r"(v[t].x), "r"(v[t].y)
                         : "memory");
        }
    }
}

// ---------------------------------------------------------------------------
// Fused dual GEMM with packed f32x2 FMA (FFMA2). A operand is fp16
// (aggregate), converted to fp32 at staging; X operand fp32. Epilogue
// optionally emits an fp16 copy of the output (for the next scatter).
// ---------------------------------------------------------------------------
#define KT 64
#define AST 68
#define GEMM_SMEM ((2 * 128 * 128 + 2 * 128 * AST) * sizeof(float))

__device__ __forceinline__ u64 pack2(float a) {
    u64 r;
    asm("mov.b64 %0, {%1, %1};" : "=l"(r) : "f"(a));
    return r;
}
__device__ __forceinline__ u64 ffma2(u64 a, u64 b, u64 c) {
    u64 d;
    asm("fma.rn.f32x2 %0, %1, %2, %3;" : "=l"(d) : "l"(a), "l"(b), "l"(c));
    return d;
}

__global__ __launch_bounds__(256, 1)
void gemm_kernel(const __half* __restrict__ A16,   // fp16 aggregate [N,128]
                 const float* __restrict__ X,      // fp32 root input [N,128]
                 const float* __restrict__ Wrel,
                 const float* __restrict__ Wroot,
                 const float* __restrict__ bias,
                 float* __restrict__ out,
                 __half* __restrict__ out16,       // optional fp16 copy
                 int relu) {
    extern __shared__ float sm[];
    float* Wr = sm;
    float* Wo = Wr + 128 * 128;
    float* As = Wo + 128 * 128;
    float* Xs = As + 128 * AST;

    int tid = threadIdx.x;
    int row0 = blockIdx.x * 128;
    int tx = tid & 15;
    int ty = tid >> 4;

    for (int i = tid; i < 128 * 128 / 4; i += 256) {
        ((float4*)Wr)[i] = ((const float4*)Wrel)[i];
        ((float4*)Wo)[i] = ((const float4*)Wroot)[i];
    }

    u64 acc[8][4];
#pragma unroll
    for (int i = 0; i < 8; i++)
#pragma unroll
        for (int j = 0; j < 4; j++) acc[i][j] = 0ull;

    for (int stage = 0; stage < 2; stage++) {
        int kb = stage * KT;
        __syncthreads();
        for (int i = tid; i < 128 * 16; i += 256) {
            int r = i >> 4, c = i & 15;
            int grow = row0 + r;
            float4 av, xv;
            if (grow < NN) {
                uint2 u = *(const uint2*)(A16 + (size_t)grow * DD + kb + c * 4);
                float2 f0 = __half22float2(*(__half2*)&u.x);
                float2 f1 = __half22float2(*(__half2*)&u.y);
                av = make_float4(f0.x, f0.y, f1.x, f1.y);
                xv = ((const float4*)(X + (size_t)grow * DD + kb))[c];
            } else {
                av = make_float4(0.f, 0.f, 0.f, 0.f);
                xv = av;
            }
            ((float4*)(As + r * AST))[c] = av;
            ((float4*)(Xs + r * AST))[c] = xv;
        }
        __syncthreads();

#pragma unroll 2
        for (int kk = 0; kk < KT; kk++) {
            const float* wrk = Wr + (kb + kk) * 128;
            const float* wok = Wo + (kb + kk) * 128;
            u64 wr2[4], wo2[4];
#pragma unroll
            for (int j = 0; j < 4; j++) {
                wr2[j] = *(const u64*)(wrk + tx * 2 + j * 32);
                wo2[j] = *(const u64*)(wok + tx * 2 + j * 32);
            }
            u64 a2[8], x2[8];
#pragma unroll
            for (int i = 0; i < 8; i++) {
                a2[i] = pack2(As[(ty * 8 + i) * AST + kk]);
                x2[i] = pack2(Xs[(ty * 8 + i) * AST + kk]);
            }
#pragma unroll
            for (int i = 0; i < 8; i++)
#pragma unroll
                for (int j = 0; j < 4; j++) {
                    acc[i][j] = ffma2(a2[i], wr2[j], acc[i][j]);
                    acc[i][j] = ffma2(x2[i], wo2[j], acc[i][j]);
                }
        }
    }

    float b0[4], b1[4];
#pragma unroll
    for (int j = 0; j < 4; j++) {
        int c = tx * 2 + j * 32;
        b0[j] = __ldg(&bias[c]);
        b1[j] = __ldg(&bias[c + 1]);
    }
#pragma unroll
    for (int i = 0; i < 8; i++) {
        int grow = row0 + ty * 8 + i;
        if (grow < NN) {
#pragma unroll
            for (int j = 0; j < 4; j++) {
                int c = tx * 2 + j * 32;
                float lo, hi;
                asm("mov.b64 {%0, %1}, %2;" : "=f"(lo), "=f"(hi) : "l"(acc[i][j]));
                lo += b0[j];
                hi += b1[j];
                if (relu) { lo = fmaxf(lo, 0.f); hi = fmaxf(hi, 0.f); }
                *(float2*)(out + (size_t)grow * DD + c) = make_float2(lo, hi);
                if (out16) {
                    __half2 hh = __floats2half2_rn(lo, hi);
                    *(__half2*)(out16 + (size_t)grow * DD + c) = hh;
                }
            }
        }
    }
}

// ---------------------------------------------------------------------------
// Launch
// ---------------------------------------------------------------------------
extern "C" void kernel_launch(void* const* d_in, const int* in_sizes, int n_in,
                              void* d_out, int out_size) {
    const float* x       = (const float*)d_in[0];
    const int*   ei      = (const int*)d_in[1];   // int32 (JAX x64 disabled)
    const float* W1_rel  = (const float*)d_in[2];
    const float* b1_rel  = (const float*)d_in[3];
    const float* W1_root = (const float*)d_in[4];
    const float* W2_rel  = (const float*)d_in[5];
    const float* b2_rel  = (const float*)d_in[6];
    const float* W2_root = (const float*)d_in[7];
    float*       out     = (float*)d_out;

    float  *h;
    __half *feat16, *agg16;
    cudaGetSymbolAddress((void**)&h, g_h);
    cudaGetSymbolAddress((void**)&feat16, g_feat16);
    cudaGetSymbolAddress((void**)&agg16, g_agg16);

    cudaFuncSetAttribute(gemm_kernel,
                         cudaFuncAttributeMaxDynamicSharedMemorySize,
                         (int)GEMM_SMEM);

    const int n4 = NN * DD / 4;                  // float4 count (fp32)
    const int n4h = NN * DD * 2 / 16;            // float4 count (fp16 buffer)
    const int cgrid = (n4 + 255) / 256;
    const int zgrid = (n4h + 255) / 256;
    const int nwarp = (EE + EPW - 1) / EPW;
    const int sgrid = (nwarp * 32 + 255) / 256;
    const int ggrid = (NN + 127) / 128;

    // x -> fp16
    tohalf_kernel<<<cgrid, 256>>>((const float4*)x, (uint2*)feat16, n4);

    // Layer 1  (gemm also emits h16 into feat16 for the next scatter)
    zero_kernel<<<zgrid, 256>>>((float4*)agg16, n4h);
    scatter16_kernel<<<sgrid, 256>>>(feat16, ei, agg16);
    gemm_kernel<<<ggrid, 256, GEMM_SMEM>>>(agg16, x, W1_rel, W1_root, b1_rel,
                                           h, feat16, 1);

    // Layer 2
    zero_kernel<<<zgrid, 256>>>((float4*)agg16, n4h);
    scatter16_kernel<<<sgrid, 256>>>(feat16, ei, agg16);
    gemm_kernel<<<ggrid, 256, GEMM_SMEM>>>(agg16, h, W2_rel, W2_root, b2_rel,
                                           out, (/*none*/__half*)nullptr, 0);
}